// round 2
// baseline (speedup 1.0000x reference)
#include <cuda_runtime.h>

#define E_EXPERTS 8
#define D_IN 256
#define H_HID 64
#define A_OUT 18
#define B_TOTAL 65536
#define R_ROWS 64           // rows per tile
#define T_THREADS 256
#define MAX_TILES (B_TOTAL / R_ROWS + E_EXPERTS)   // 1032, static grid

// ---- shared memory layout (float offsets) ----
#define W1_OFF 0                       // 256*64 = 16384
#define W2_OFF 16384                   // 4096
#define W3_OFF 20480
#define W4_OFF 24576
#define W5_OFF 28672
#define W6_OFF 32768                   // 64*18 = 1152
#define B1_OFF 33920
#define B2_OFF 33984
#define B3_OFF 34048
#define B4_OFF 34112
#define B5_OFF 34176
#define B6_OFF 34240                   // 18
#define XS_OFF 34304
#define XS_STRIDE 260                  // 256 + 4 pad: row-delta 4*260 ≡ 16 mod 32 banks
#define HS_OFF (XS_OFF + R_ROWS * XS_STRIDE)   // 50944
#define H_STRIDE 68                    // 64 + 4 pad: row-delta 4*68 ≡ 16 mod 32 banks
#define SMEM_FLOATS (HS_OFF + R_ROWS * H_STRIDE)  // 55296
#define SMEM_BYTES (SMEM_FLOATS * 4)              // 221184

// ---- scratch (static device globals; no runtime allocation) ----
__device__ int g_count[E_EXPERTS];
__device__ int g_tiles[E_EXPERTS + 1];
__device__ int g_rowlist[E_EXPERTS * B_TOTAL];

// ============================================================
// Kernel 0: zero per-expert counters (must run every launch: graph replays)
// ============================================================
__global__ void zero_counts_kernel() {
    if (threadIdx.x < E_EXPERTS) g_count[threadIdx.x] = 0;
}

// ============================================================
// Kernel 1: bucketize rows by expert, block-aggregated atomics
// grid: B_TOTAL / 256 blocks x 256 threads
// ============================================================
__global__ void bucket_kernel(const int* __restrict__ rm) {
    __shared__ int s_cnt[E_EXPERTS];
    __shared__ int s_base[E_EXPERTS];
    int tid = threadIdx.x;
    int gid = blockIdx.x * blockDim.x + tid;
    if (tid < E_EXPERTS) s_cnt[tid] = 0;
    __syncthreads();
    int e = rm[gid];
    int rank = atomicAdd(&s_cnt[e], 1);
    __syncthreads();
    if (tid < E_EXPERTS) s_base[tid] = atomicAdd(&g_count[tid], s_cnt[tid]);
    __syncthreads();
    g_rowlist[e * B_TOTAL + s_base[e] + rank] = gid;
}

// ============================================================
// Kernel 2: tile partition (prefix over per-expert tile counts)
// ============================================================
__global__ void partition_kernel() {
    int acc = 0;
    for (int i = 0; i < E_EXPERTS; i++) {
        g_tiles[i] = acc;
        acc += (g_count[i] + R_ROWS - 1) / R_ROWS;
    }
    g_tiles[E_EXPERTS] = acc;
}

// ============================================================
// Hidden-layer 64x64 GEMM tile (K=64), 4x4 micro-tile per thread
// ============================================================
__device__ __forceinline__ void layer_h(float* __restrict__ sm, int in_off, int out_off,
                                        int w_off, int b_off, int tx, int ty) {
    const int r0 = ty * 4, c0 = tx * 4;
    float acc[4][4];
    {
        float4 bv = *(const float4*)&sm[b_off + c0];
        #pragma unroll
        for (int i = 0; i < 4; i++) {
            acc[i][0] = bv.x; acc[i][1] = bv.y; acc[i][2] = bv.z; acc[i][3] = bv.w;
        }
    }
    #pragma unroll 8
    for (int k = 0; k < H_HID; k++) {
        float4 w = *(const float4*)&sm[w_off + k * H_HID + c0];
        float a0 = sm[in_off + (r0 + 0) * H_STRIDE + k];
        float a1 = sm[in_off + (r0 + 1) * H_STRIDE + k];
        float a2 = sm[in_off + (r0 + 2) * H_STRIDE + k];
        float a3 = sm[in_off + (r0 + 3) * H_STRIDE + k];
        acc[0][0] += a0 * w.x; acc[0][1] += a0 * w.y; acc[0][2] += a0 * w.z; acc[0][3] += a0 * w.w;
        acc[1][0] += a1 * w.x; acc[1][1] += a1 * w.y; acc[1][2] += a1 * w.z; acc[1][3] += a1 * w.w;
        acc[2][0] += a2 * w.x; acc[2][1] += a2 * w.y; acc[2][2] += a2 * w.z; acc[2][3] += a2 * w.w;
        acc[3][0] += a3 * w.x; acc[3][1] += a3 * w.y; acc[3][2] += a3 * w.z; acc[3][3] += a3 * w.w;
    }
    #pragma unroll
    for (int i = 0; i < 4; i++) {
        float4 v;
        v.x = fmaxf(acc[i][0], 0.0f);
        v.y = fmaxf(acc[i][1], 0.0f);
        v.z = fmaxf(acc[i][2], 0.0f);
        v.w = fmaxf(acc[i][3], 0.0f);
        *(float4*)&sm[out_off + (r0 + i) * H_STRIDE + c0] = v;
    }
}

// ============================================================
// Kernel 3: per-(expert,row-tile) 6-layer MLP, all weights in SMEM
// ============================================================
__global__ __launch_bounds__(T_THREADS, 1)
void moe_compute_kernel(const float* __restrict__ state,
                        const float* __restrict__ W1, const float* __restrict__ b1,
                        const float* __restrict__ W2, const float* __restrict__ b2,
                        const float* __restrict__ W3, const float* __restrict__ b3,
                        const float* __restrict__ W4, const float* __restrict__ b4,
                        const float* __restrict__ W5, const float* __restrict__ b5,
                        const float* __restrict__ W6, const float* __restrict__ b6,
                        float* __restrict__ out) {
    int blk = blockIdx.x;
    if (blk >= g_tiles[E_EXPERTS]) return;
    int e = 0;
    while (blk >= g_tiles[e + 1]) e++;
    int tile = blk - g_tiles[e];
    int cnt = g_count[e];
    int base = tile * R_ROWS;

    extern __shared__ float sm[];
    __shared__ int rowidx[R_ROWS];

    int tid = threadIdx.x;

    // ---- stage expert weights (float4, coalesced) ----
    {
        const float4* s1 = (const float4*)(W1 + (size_t)e * D_IN * H_HID);
        float4* d1 = (float4*)(sm + W1_OFF);
        for (int i = tid; i < D_IN * H_HID / 4; i += T_THREADS) d1[i] = s1[i];

        const float* Wmid[4] = {W2, W3, W4, W5};
        const int moff[4] = {W2_OFF, W3_OFF, W4_OFF, W5_OFF};
        #pragma unroll
        for (int l = 0; l < 4; l++) {
            const float4* s = (const float4*)(Wmid[l] + (size_t)e * H_HID * H_HID);
            float4* d = (float4*)(sm + moff[l]);
            for (int i = tid; i < H_HID * H_HID / 4; i += T_THREADS) d[i] = s[i];
        }
        const float4* s6 = (const float4*)(W6 + (size_t)e * H_HID * A_OUT);
        float4* d6 = (float4*)(sm + W6_OFF);
        for (int i = tid; i < H_HID * A_OUT / 4; i += T_THREADS) d6[i] = s6[i];

        if (tid < H_HID) {
            sm[B1_OFF + tid] = b1[e * H_HID + tid];
            sm[B2_OFF + tid] = b2[e * H_HID + tid];
            sm[B3_OFF + tid] = b3[e * H_HID + tid];
            sm[B4_OFF + tid] = b4[e * H_HID + tid];
            sm[B5_OFF + tid] = b5[e * H_HID + tid];
        }
        if (tid < A_OUT) sm[B6_OFF + tid] = b6[e * A_OUT + tid];
    }

    // ---- row indices for this tile ----
    if (tid < R_ROWS) {
        int g = base + tid;
        rowidx[tid] = (g < cnt) ? g_rowlist[e * B_TOTAL + g] : -1;
    }
    __syncthreads();

    // ---- gather x tile into SMEM (float4, coalesced per row) ----
    {
        int warp = tid >> 5, lane = tid & 31;
        for (int r = warp; r < R_ROWS; r += 8) {
            int src = rowidx[r];
            if (src >= 0) {
                const float4* xp = (const float4*)(state + (size_t)src * D_IN);
                float4* xd = (float4*)(sm + XS_OFF + r * XS_STRIDE);
                xd[lane] = xp[lane];
                xd[lane + 32] = xp[lane + 32];
            }
        }
    }
    __syncthreads();

    const int tx = tid & 15, ty = tid >> 4;
    const int r0 = ty * 4, c0 = tx * 4;

    // ---- layer 1: [64x256] x [256x64] ----
    {
        float acc[4][4];
        float4 bv = *(const float4*)&sm[B1_OFF + c0];
        #pragma unroll
        for (int i = 0; i < 4; i++) {
            acc[i][0] = bv.x; acc[i][1] = bv.y; acc[i][2] = bv.z; acc[i][3] = bv.w;
        }
        #pragma unroll 4
        for (int k = 0; k < D_IN; k++) {
            float4 w = *(const float4*)&sm[W1_OFF + k * H_HID + c0];
            float a0 = sm[XS_OFF + (r0 + 0) * XS_STRIDE + k];
            float a1 = sm[XS_OFF + (r0 + 1) * XS_STRIDE + k];
            float a2 = sm[XS_OFF + (r0 + 2) * XS_STRIDE + k];
            float a3 = sm[XS_OFF + (r0 + 3) * XS_STRIDE + k];
            acc[0][0] += a0 * w.x; acc[0][1] += a0 * w.y; acc[0][2] += a0 * w.z; acc[0][3] += a0 * w.w;
            acc[1][0] += a1 * w.x; acc[1][1] += a1 * w.y; acc[1][2] += a1 * w.z; acc[1][3] += a1 * w.w;
            acc[2][0] += a2 * w.x; acc[2][1] += a2 * w.y; acc[2][2] += a2 * w.z; acc[2][3] += a2 * w.w;
            acc[3][0] += a3 * w.x; acc[3][1] += a3 * w.y; acc[3][2] += a3 * w.z; acc[3][3] += a3 * w.w;
        }
        #pragma unroll
        for (int i = 0; i < 4; i++) {
            float4 v;
            v.x = fmaxf(acc[i][0], 0.0f);
            v.y = fmaxf(acc[i][1], 0.0f);
            v.z = fmaxf(acc[i][2], 0.0f);
            v.w = fmaxf(acc[i][3], 0.0f);
            *(float4*)&sm[HS_OFF + (r0 + i) * H_STRIDE + c0] = v;
        }
    }
    __syncthreads();

    // ---- layers 2..5: ping-pong between HS and XS regions (stride 68) ----
    layer_h(sm, HS_OFF, XS_OFF, W2_OFF, B2_OFF, tx, ty);
    __syncthreads();
    layer_h(sm, XS_OFF, HS_OFF, W3_OFF, B3_OFF, tx, ty);
    __syncthreads();
    layer_h(sm, HS_OFF, XS_OFF, W4_OFF, B4_OFF, tx, ty);
    __syncthreads();
    layer_h(sm, XS_OFF, HS_OFF, W5_OFF, B5_OFF, tx, ty);
    __syncthreads();

    // ---- layer 6: [64x64] x [64x18], no relu, scatter to output ----
    for (int o = tid; o < H_HID * A_OUT; o += T_THREADS) {
        int r = o / A_OUT;
        int c = o - r * A_OUT;
        float acc = sm[B6_OFF + c];
        #pragma unroll
        for (int k = 0; k < H_HID; k++)
            acc += sm[HS_OFF + r * H_STRIDE + k] * sm[W6_OFF + k * A_OUT + c];
        int src = rowidx[r];
        if (src >= 0) out[(size_t)src * A_OUT + c] = acc;
    }
}

// ============================================================
// Launch
// ============================================================
extern "C" void kernel_launch(void* const* d_in, const int* in_sizes, int n_in,
                              void* d_out, int out_size) {
    (void)in_sizes; (void)n_in; (void)out_size;
    const float* state = (const float*)d_in[0];
    const int*   rm    = (const int*)d_in[1];
    const float* W1 = (const float*)d_in[2];  const float* b1 = (const float*)d_in[3];
    const float* W2 = (const float*)d_in[4];  const float* b2 = (const float*)d_in[5];
    const float* W3 = (const float*)d_in[6];  const float* b3 = (const float*)d_in[7];
    const float* W4 = (const float*)d_in[8];  const float* b4 = (const float*)d_in[9];
    const float* W5 = (const float*)d_in[10]; const float* b5 = (const float*)d_in[11];
    const float* W6 = (const float*)d_in[12]; const float* b6 = (const float*)d_in[13];
    float* out = (float*)d_out;

    cudaFuncSetAttribute(moe_compute_kernel,
                         cudaFuncAttributeMaxDynamicSharedMemorySize, SMEM_BYTES);

    zero_counts_kernel<<<1, 32>>>();
    bucket_kernel<<<B_TOTAL / T_THREADS, T_THREADS>>>(rm);
    partition_kernel<<<1, 1>>>();
    moe_compute_kernel<<<MAX_TILES, T_THREADS, SMEM_BYTES>>>(
        state, W1, b1, W2, b2, W3, b3, W4, b4, W5, b5, W6, b6, out);
}

// round 5
// speedup vs baseline: 1.0379x; 1.0379x over previous
#include <cuda_runtime.h>

typedef unsigned long long ull;

#define E_EXPERTS 8
#define D_IN 256
#define H_HID 64
#define A_OUT 18
#define B_TOTAL 65536
#define R_ROWS 64
#define T_THREADS 512

// ---- shared memory layout (float offsets) ----
#define W1_OFF 0                        // 256*64
#define W2_OFF 16384
#define W3_OFF 20480
#define W4_OFF 24576
#define W5_OFF 28672
#define W6T_OFF 32768                   // transposed [A][H] stride 68 -> 1224
#define B1_OFF 33992
#define B2_OFF 34056
#define B3_OFF 34120
#define B4_OFF 34184
#define B5_OFF 34248
#define B6_OFF 34312                    // 18
#define XS_OFF 34336
#define XS_STRIDE 260
#define HS_OFF (XS_OFF + R_ROWS * XS_STRIDE)     // 50976
#define H_STRIDE 68
#define SMEM_FLOATS (HS_OFF + R_ROWS * H_STRIDE) // 55328
#define SMEM_BYTES (SMEM_FLOATS * 4)             // 221312

// ---- scratch ----
__device__ int g_count[E_EXPERTS];
__device__ int g_tiles[E_EXPERTS + 1];
__device__ int g_rowlist[E_EXPERTS * B_TOTAL];

// ---- packed fp32x2 helpers ----
__device__ __forceinline__ ull pack2(float x, float y) {
    ull r; asm("mov.b64 %0, {%1, %2};" : "=l"(r) : "f"(x), "f"(y)); return r;
}
__device__ __forceinline__ void ffma2(ull& d, ull a, ull b) {
    asm("fma.rn.f32x2 %0, %1, %2, %0;" : "+l"(d) : "l"(a), "l"(b));
}
__device__ __forceinline__ float2 unpack2(ull v) {
    float2 f; asm("mov.b64 {%0, %1}, %2;" : "=f"(f.x), "=f"(f.y) : "l"(v)); return f;
}

// ============================================================
__global__ void zero_counts_kernel() {
    if (threadIdx.x < E_EXPERTS) g_count[threadIdx.x] = 0;
}

// grid: B/1024 blocks x 256 threads, 4 rows per thread (int4 load)
__global__ void bucket_kernel(const int* __restrict__ rm) {
    __shared__ int s_cnt[E_EXPERTS];
    __shared__ int s_base[E_EXPERTS];
    int tid = threadIdx.x;
    int gid4 = blockIdx.x * blockDim.x + tid;
    if (tid < E_EXPERTS) s_cnt[tid] = 0;
    __syncthreads();
    int4 ev = ((const int4*)rm)[gid4];
    int e[4] = {ev.x, ev.y, ev.z, ev.w};
    int rank[4];
    #pragma unroll
    for (int i = 0; i < 4; i++) rank[i] = atomicAdd(&s_cnt[e[i]], 1);
    __syncthreads();
    if (tid < E_EXPERTS) s_base[tid] = atomicAdd(&g_count[tid], s_cnt[tid]);
    __syncthreads();
    #pragma unroll
    for (int i = 0; i < 4; i++)
        g_rowlist[e[i] * B_TOTAL + s_base[e[i]] + rank[i]] = gid4 * 4 + i;
}

__global__ void partition_kernel() {
    int acc = 0;
    for (int i = 0; i < E_EXPERTS; i++) {
        g_tiles[i] = acc;
        acc += (g_count[i] + R_ROWS - 1) / R_ROWS;
    }
    g_tiles[E_EXPERTS] = acc;
}

// ============================================================
// Hidden-layer 64x64 GEMM tile (K=64), 2x4 micro-tile, f32x2 packed FMA
// ============================================================
__device__ __forceinline__ void layer_h(float* __restrict__ sm, int in_off, int out_off,
                                        int w_off, int b_off, int tx, int ty) {
    const int r0 = ty * 2, c0 = tx * 4;
    ull acc00, acc01, acc10, acc11;
    {
        ull blo = *(const ull*)&sm[b_off + c0];
        ull bhi = *(const ull*)&sm[b_off + c0 + 2];
        acc00 = blo; acc01 = bhi; acc10 = blo; acc11 = bhi;
    }
    const float* arow0 = &sm[in_off + r0 * H_STRIDE];
    const float* arow1 = arow0 + H_STRIDE;
    #pragma unroll 8
    for (int k0 = 0; k0 < H_HID; k0 += 4) {
        float4 a0 = *(const float4*)(arow0 + k0);
        float4 a1 = *(const float4*)(arow1 + k0);
        #pragma unroll
        for (int kk = 0; kk < 4; kk++) {
            const float* wp = &sm[w_off + (k0 + kk) * H_HID + c0];
            ull wlo = *(const ull*)wp;
            ull whi = *(const ull*)(wp + 2);
            float av0 = (&a0.x)[kk];
            float av1 = (&a1.x)[kk];
            ull aa0 = pack2(av0, av0);
            ull aa1 = pack2(av1, av1);
            ffma2(acc00, aa0, wlo); ffma2(acc01, aa0, whi);
            ffma2(acc10, aa1, wlo); ffma2(acc11, aa1, whi);
        }
    }
    {
        float2 lo = unpack2(acc00), hi = unpack2(acc01);
        float4 v = {fmaxf(lo.x, 0.f), fmaxf(lo.y, 0.f), fmaxf(hi.x, 0.f), fmaxf(hi.y, 0.f)};
        *(float4*)&sm[out_off + r0 * H_STRIDE + c0] = v;
    }
    {
        float2 lo = unpack2(acc10), hi = unpack2(acc11);
        float4 v = {fmaxf(lo.x, 0.f), fmaxf(lo.y, 0.f), fmaxf(hi.x, 0.f), fmaxf(hi.y, 0.f)};
        *(float4*)&sm[out_off + (r0 + 1) * H_STRIDE + c0] = v;
    }
}

// ============================================================
// Persistent per-SM kernel: contiguous tile chunks, weights restaged only
// on expert change.
// ============================================================
__global__ __launch_bounds__(T_THREADS, 1)
void moe_persistent_kernel(const float* __restrict__ state,
                           const float* __restrict__ W1, const float* __restrict__ b1,
                           const float* __restrict__ W2, const float* __restrict__ b2,
                           const float* __restrict__ W3, const float* __restrict__ b3,
                           const float* __restrict__ W4, const float* __restrict__ b4,
                           const float* __restrict__ W5, const float* __restrict__ b5,
                           const float* __restrict__ W6, const float* __restrict__ b6,
                           float* __restrict__ out) {
    extern __shared__ float sm[];
    __shared__ int rowidx[R_ROWS];

    int tid = threadIdx.x;
    int total = g_tiles[E_EXPERTS];
    int chunk = (total + gridDim.x - 1) / gridDim.x;
    int t0 = blockIdx.x * chunk;
    int t1 = min(t0 + chunk, total);
    if (t0 >= t1) return;

    const int tx = tid & 15, ty = tid >> 4;
    int cur_e = -1;

    for (int t = t0; t < t1; t++) {
        int e = 0;
        while (t >= g_tiles[e + 1]) e++;

        __syncthreads();  // previous tile fully consumed before smem overwrite

        if (e != cur_e) {
            cur_e = e;
            // stage W1
            const float4* s1 = (const float4*)(W1 + (size_t)e * D_IN * H_HID);
            float4* d1 = (float4*)(sm + W1_OFF);
            for (int i = tid; i < D_IN * H_HID / 4; i += T_THREADS) d1[i] = s1[i];
            // stage W2..W5
            const float* Wmid[4] = {W2, W3, W4, W5};
            const int moff[4] = {W2_OFF, W3_OFF, W4_OFF, W5_OFF};
            #pragma unroll
            for (int l = 0; l < 4; l++) {
                const float4* s = (const float4*)(Wmid[l] + (size_t)e * H_HID * H_HID);
                float4* d = (float4*)(sm + moff[l]);
                for (int i = tid; i < H_HID * H_HID / 4; i += T_THREADS) d[i] = s[i];
            }
            // stage W6 transposed: [A][H] with stride H_STRIDE
            const float* s6 = W6 + (size_t)e * H_HID * A_OUT;
            for (int i = tid; i < H_HID * A_OUT; i += T_THREADS) {
                int k = i / A_OUT, c = i - k * A_OUT;
                sm[W6T_OFF + c * H_STRIDE + k] = s6[i];
            }
            if (tid < H_HID) {
                sm[B1_OFF + tid] = b1[e * H_HID + tid];
                sm[B2_OFF + tid] = b2[e * H_HID + tid];
                sm[B3_OFF + tid] = b3[e * H_HID + tid];
                sm[B4_OFF + tid] = b4[e * H_HID + tid];
                sm[B5_OFF + tid] = b5[e * H_HID + tid];
            }
            if (tid < A_OUT) sm[B6_OFF + tid] = b6[e * A_OUT + tid];
        }

        int tile = t - g_tiles[e];
        int cnt = g_count[e];
        int base = tile * R_ROWS;

        if (tid < R_ROWS) {
            int g = base + tid;
            rowidx[tid] = (g < cnt) ? g_rowlist[e * B_TOTAL + g] : -1;
        }
        __syncthreads();

        // gather x tile (float4 coalesced per row; 16 warps, 4 rows each)
        {
            int warp = tid >> 5, lane = tid & 31;
            for (int r = warp; r < R_ROWS; r += 16) {
                int src = rowidx[r];
                if (src >= 0) {
                    const float4* xp = (const float4*)(state + (size_t)src * D_IN);
                    float4* xd = (float4*)(sm + XS_OFF + r * XS_STRIDE);
                    xd[lane] = xp[lane];
                    xd[lane + 32] = xp[lane + 32];
                }
            }
        }
        __syncthreads();

        // ---- layer 1: [64x256]x[256x64] ----
        {
            const int r0 = ty * 2, c0 = tx * 4;
            ull acc00, acc01, acc10, acc11;
            {
                ull blo = *(const ull*)&sm[B1_OFF + c0];
                ull bhi = *(const ull*)&sm[B1_OFF + c0 + 2];
                acc00 = blo; acc01 = bhi; acc10 = blo; acc11 = bhi;
            }
            const float* arow0 = &sm[XS_OFF + r0 * XS_STRIDE];
            const float* arow1 = arow0 + XS_STRIDE;
            #pragma unroll 8
            for (int k0 = 0; k0 < D_IN; k0 += 4) {
                float4 a0 = *(const float4*)(arow0 + k0);
                float4 a1 = *(const float4*)(arow1 + k0);
                #pragma unroll
                for (int kk = 0; kk < 4; kk++) {
                    const float* wp = &sm[W1_OFF + (k0 + kk) * H_HID + c0];
                    ull wlo = *(const ull*)wp;
                    ull whi = *(const ull*)(wp + 2);
                    float av0 = (&a0.x)[kk];
                    float av1 = (&a1.x)[kk];
                    ull aa0 = pack2(av0, av0);
                    ull aa1 = pack2(av1, av1);
                    ffma2(acc00, aa0, wlo); ffma2(acc01, aa0, whi);
                    ffma2(acc10, aa1, wlo); ffma2(acc11, aa1, whi);
                }
            }
            {
                float2 lo = unpack2(acc00), hi = unpack2(acc01);
                float4 v = {fmaxf(lo.x, 0.f), fmaxf(lo.y, 0.f), fmaxf(hi.x, 0.f), fmaxf(hi.y, 0.f)};
                *(float4*)&sm[HS_OFF + r0 * H_STRIDE + c0] = v;
            }
            {
                float2 lo = unpack2(acc10), hi = unpack2(acc11);
                float4 v = {fmaxf(lo.x, 0.f), fmaxf(lo.y, 0.f), fmaxf(hi.x, 0.f), fmaxf(hi.y, 0.f)};
                *(float4*)&sm[HS_OFF + (r0 + 1) * H_STRIDE + c0] = v;
            }
        }
        __syncthreads();

        layer_h(sm, HS_OFF, XS_OFF, W2_OFF, B2_OFF, tx, ty);
        __syncthreads();
        layer_h(sm, XS_OFF, HS_OFF, W3_OFF, B3_OFF, tx, ty);
        __syncthreads();
        layer_h(sm, HS_OFF, XS_OFF, W4_OFF, B4_OFF, tx, ty);
        __syncthreads();
        layer_h(sm, XS_OFF, HS_OFF, W5_OFF, B5_OFF, tx, ty);
        __syncthreads();

        // ---- layer 6: [64x64]x[64x18] with transposed W6, scatter out ----
        for (int o = tid; o < R_ROWS * A_OUT; o += T_THREADS) {
            int r = o / A_OUT;
            int c = o - r * A_OUT;
            int src = rowidx[r];
            if (src < 0) continue;
            float acc = sm[B6_OFF + c];
            const float* ar = &sm[HS_OFF + r * H_STRIDE];
            const float* wr = &sm[W6T_OFF + c * H_STRIDE];
            #pragma unroll
            for (int k0 = 0; k0 < H_HID; k0 += 4) {
                float4 a = *(const float4*)(ar + k0);
                float4 w = *(const float4*)(wr + k0);
                acc += a.x * w.x + a.y * w.y + a.z * w.z + a.w * w.w;
            }
            out[(size_t)src * A_OUT + c] = acc;
        }
        // loop-top __syncthreads protects rowidx/XS/weights for next tile
    }
}

// ============================================================
extern "C" void kernel_launch(void* const* d_in, const int* in_sizes, int n_in,
                              void* d_out, int out_size) {
    (void)in_sizes; (void)n_in; (void)out_size;
    const float* state = (const float*)d_in[0];
    const int*   rm    = (const int*)d_in[1];
    const float* W1 = (const float*)d_in[2];  const float* b1 = (const float*)d_in[3];
    const float* W2 = (const float*)d_in[4];  const float* b2 = (const float*)d_in[5];
    const float* W3 = (const float*)d_in[6];  const float* b3 = (const float*)d_in[7];
    const float* W4 = (const float*)d_in[8];  const float* b4 = (const float*)d_in[9];
    const float* W5 = (const float*)d_in[10]; const float* b5 = (const float*)d_in[11];
    const float* W6 = (const float*)d_in[12]; const float* b6 = (const float*)d_in[13];
    float* out = (float*)d_out;

    int sm_count = 148;
    cudaDeviceGetAttribute(&sm_count, cudaDevAttrMultiProcessorCount, 0);

    cudaFuncSetAttribute(moe_persistent_kernel,
                         cudaFuncAttributeMaxDynamicSharedMemorySize, SMEM_BYTES);

    zero_counts_kernel<<<1, 32>>>();
    bucket_kernel<<<B_TOTAL / (256 * 4), 256>>>(rm);
    partition_kernel<<<1, 1>>>();
    moe_persistent_kernel<<<sm_count, T_THREADS, SMEM_BYTES>>>(
        state, W1, b1, W2, b2, W3, b3, W4, b4, W5, b5, W6, b6, out);
}